// round 14
// baseline (speedup 1.0000x reference)
#include <cuda_runtime.h>
#include <cuda_bf16.h>

#define D 128
#define MAX_N 100000
#define MAX_E 1600000
#define WTP 132   // padded W^T row stride (floats); 66 ull per k row

typedef unsigned long long ull;

// Scratch (device globals — no allocations allowed)
__device__ __nv_bfloat16 g_fb[(size_t)MAX_N * D];  // bf16 features
__device__ float g_total[D];
__device__ int   g_cnt[MAX_N];                     // degrees, then fill cursor
__device__ int   g_off[MAX_N + 1];                 // CSR offsets
__device__ int   g_eidx[MAX_E];                    // src ids bucketed by dst
__device__ int   g_bsum[1024];                     // scan block sums

// ---------------------------------------------------------------------------
__global__ void k_init(int N) {
    int i = blockIdx.x * blockDim.x + threadIdx.x;
    if (i < N) g_cnt[i] = 0;
    if (i < D) g_total[i] = 0.f;
}

// column sums + bf16 conversion fused (one pass over features)
__global__ void k_total(const float* __restrict__ feat, int N) {
    int c = threadIdx.x;
    float s = 0.f;
    for (int r = blockIdx.x; r < N; r += gridDim.x) {
        float v = feat[(size_t)r * D + c];
        s += v;
        g_fb[(size_t)r * D + c] = __float2bfloat16(v);
    }
    atomicAdd(&g_total[c], s);
}

__global__ void k_degree(const int* __restrict__ dst, int E) {
    int e = blockIdx.x * blockDim.x + threadIdx.x;
    if (e < E) atomicAdd(&g_cnt[dst[e]], 1);
}

// scan1: per-1024-chunk sums
__global__ void k_scan1(int N) {
    __shared__ int ss[256];
    int base = blockIdx.x * 1024;
    int t = threadIdx.x;
    int s = 0;
    #pragma unroll
    for (int j = 0; j < 4; j++) {
        int i = base + t + j * 256;
        if (i < N) s += g_cnt[i];
    }
    ss[t] = s; __syncthreads();
    for (int o = 128; o; o >>= 1) { if (t < o) ss[t] += ss[t + o]; __syncthreads(); }
    if (t == 0) g_bsum[blockIdx.x] = ss[0];
}

// scan2: exclusive scan of block sums, plus g_off[N] = E
__global__ void k_scan2(int SB, int E, int N) {
    __shared__ int ss[1024];
    int t = threadIdx.x;
    for (int i = t; i < SB; i += blockDim.x) ss[i] = g_bsum[i];
    __syncthreads();
    if (t == 0) {
        int run = 0;
        for (int i = 0; i < SB; i++) { int v = ss[i]; ss[i] = run; run += v; }
        g_off[N] = E;
    }
    __syncthreads();
    for (int i = t; i < SB; i += blockDim.x) g_bsum[i] = ss[i];
}

// scan3: per-chunk exclusive scan + global base -> g_off, cursor init
__global__ void k_scan3(int N) {
    __shared__ int ss[256];
    int base = blockIdx.x * 1024;
    int t = threadIdx.x;
    int c[4]; int s = 0;
    #pragma unroll
    for (int j = 0; j < 4; j++) {
        int i = base + t * 4 + j;
        c[j] = (i < N) ? g_cnt[i] : 0;
        s += c[j];
    }
    ss[t] = s; __syncthreads();
    for (int o = 1; o < 256; o <<= 1) {
        int v = (t >= o) ? ss[t - o] : 0;
        __syncthreads();
        ss[t] += v;
        __syncthreads();
    }
    int run = g_bsum[blockIdx.x] + (ss[t] - s);
    #pragma unroll
    for (int j = 0; j < 4; j++) {
        int i = base + t * 4 + j;
        if (i < N) { g_off[i] = run; g_cnt[i] = run; }
        run += c[j];
    }
}

__global__ void k_fill(const int* __restrict__ src, const int* __restrict__ dst, int E) {
    int e = blockIdx.x * blockDim.x + threadIdx.x;
    if (e < E) {
        int pos = atomicAdd(&g_cnt[dst[e]], 1);
        g_eidx[pos] = src[e];
    }
}

// ---------------------------------------------------------------------------
// FUSED: gather (bf16) + subtract + L2-normalize -> smem; then GEMM
// out = h_norm @ W^T + b.  One CTA = 256-row tile, 512 threads.
// Phase 1: 16 warps x 16 rows each, h written straight to skewed shH.
// Phase 2: f32x2 column-paired GEMM (8 rows x 4 col-pairs per thread).
// ---------------------------------------------------------------------------
__global__ __launch_bounds__(512, 1)
void k_fused(const float* __restrict__ W, const float* __restrict__ b,
             float* __restrict__ out, int N) {
    extern __shared__ float sh[];
    float* shWT = sh;                              // [D][WTP]
    float* shH  = sh + D * WTP;                    // [256][128] + skew 4/8rows
    const ull* shWTu = reinterpret_cast<const ull*>(shWT);

    int tid = threadIdx.x;

    // Stage W transposed: shWT[k*WTP + c] = W[c][k]
    for (int idx = tid; idx < D * D; idx += 512) {
        int c = idx >> 7;
        int k = idx & (D - 1);
        shWT[k * WTP + c] = W[idx];
    }

    int row0 = blockIdx.x * 256;
    int w    = tid >> 5;       // warp 0..15
    int lane = tid & 31;

    // ---- Phase 1: gather + normalize 16 rows per warp ----
    float4 tv = reinterpret_cast<const float4*>(g_total)[lane];
    #pragma unroll 1
    for (int rr = 0; rr < 16; rr++) {
        int r = (w << 4) + rr;             // 0..255 within tile
        int row = row0 + r;
        float4 h = make_float4(0.f, 0.f, 0.f, 0.f);
        if (row < N) {
            int beg = g_off[row], end = g_off[row + 1];
            float4 a0 = make_float4(0.f, 0.f, 0.f, 0.f);
            float4 a1 = make_float4(0.f, 0.f, 0.f, 0.f);
            int e = beg;
            for (; e + 4 <= end; e += 4) {
                int s0 = g_eidx[e], s1 = g_eidx[e + 1];
                int s2 = g_eidx[e + 2], s3 = g_eidx[e + 3];
                ull p0 = *(const ull*)(g_fb + (size_t)s0 * D + lane * 4);
                ull p1 = *(const ull*)(g_fb + (size_t)s1 * D + lane * 4);
                ull p2 = *(const ull*)(g_fb + (size_t)s2 * D + lane * 4);
                ull p3 = *(const ull*)(g_fb + (size_t)s3 * D + lane * 4);
                {
                    float2 f0 = __bfloat1622float2(*(__nv_bfloat162*)&p0);
                    float2 f1 = __bfloat1622float2(*((__nv_bfloat162*)&p0 + 1));
                    a0.x += f0.x; a0.y += f0.y; a0.z += f1.x; a0.w += f1.y;
                }
                {
                    float2 f0 = __bfloat1622float2(*(__nv_bfloat162*)&p1);
                    float2 f1 = __bfloat1622float2(*((__nv_bfloat162*)&p1 + 1));
                    a1.x += f0.x; a1.y += f0.y; a1.z += f1.x; a1.w += f1.y;
                }
                {
                    float2 f0 = __bfloat1622float2(*(__nv_bfloat162*)&p2);
                    float2 f1 = __bfloat1622float2(*((__nv_bfloat162*)&p2 + 1));
                    a0.x += f0.x; a0.y += f0.y; a0.z += f1.x; a0.w += f1.y;
                }
                {
                    float2 f0 = __bfloat1622float2(*(__nv_bfloat162*)&p3);
                    float2 f1 = __bfloat1622float2(*((__nv_bfloat162*)&p3 + 1));
                    a1.x += f0.x; a1.y += f0.y; a1.z += f1.x; a1.w += f1.y;
                }
            }
            for (; e < end; e++) {
                int s0 = g_eidx[e];
                ull p0 = *(const ull*)(g_fb + (size_t)s0 * D + lane * 4);
                float2 f0 = __bfloat1622float2(*(__nv_bfloat162*)&p0);
                float2 f1 = __bfloat1622float2(*((__nv_bfloat162*)&p0 + 1));
                a0.x += f0.x; a0.y += f0.y; a0.z += f1.x; a0.w += f1.y;
            }
            a0.x += a1.x; a0.y += a1.y; a0.z += a1.z; a0.w += a1.w;

            h.x = tv.x - a0.x; h.y = tv.y - a0.y;
            h.z = tv.z - a0.z; h.w = tv.w - a0.w;
            float ssum = h.x * h.x + h.y * h.y + h.z * h.z + h.w * h.w;
            #pragma unroll
            for (int o = 16; o; o >>= 1) ssum += __shfl_xor_sync(0xffffffffu, ssum, o);
            float inv = 1.f / fmaxf(sqrtf(ssum), 1e-12f);
            h.x *= inv; h.y *= inv; h.z *= inv; h.w *= inv;
        }
        *reinterpret_cast<float4*>(shH + r * D + (r >> 3) * 4 + lane * 4) = h;
    }
    __syncthreads();

    // ---- Phase 2: GEMM ----
    int tr = tid >> 4;       // 0..31 -> rows tr*8..+7
    int tc = tid & 15;       // col-pairs tc + 16*j, j=0..3

    ull acc[8][4];
    #pragma unroll
    for (int i = 0; i < 8; i++)
        #pragma unroll
        for (int j = 0; j < 4; j++) acc[i][j] = 0ull;

    const float* hbase = shH + (tr << 3) * D + (tr << 2);   // skew = tr*4
    const ull* wbase = shWTu + tc;

    #pragma unroll 2
    for (int k = 0; k < D; k++) {
        ull wv[4];
        const ull* wrow = wbase + k * (WTP / 2);
        #pragma unroll
        for (int j = 0; j < 4; j++) wv[j] = wrow[16 * j];
        #pragma unroll
        for (int i = 0; i < 8; i++) {
            float hs = hbase[i * D + k];
            ull hd;
            asm("mov.b64 %0, {%1, %1};" : "=l"(hd) : "f"(hs));
            #pragma unroll
            for (int j = 0; j < 4; j++)
                asm("fma.rn.f32x2 %0, %1, %2, %0;"
                    : "+l"(acc[i][j]) : "l"(hd), "l"(wv[j]));
        }
    }

    float2 bv[4];
    #pragma unroll
    for (int j = 0; j < 4; j++)
        bv[j] = *reinterpret_cast<const float2*>(b + 2 * (tc + 16 * j));

    #pragma unroll
    for (int i = 0; i < 8; i++) {
        int row = row0 + (tr << 3) + i;
        if (row < N) {
            float* op = out + (size_t)row * D;
            #pragma unroll
            for (int j = 0; j < 4; j++) {
                float lo = __uint_as_float((unsigned)(acc[i][j] & 0xffffffffu));
                float hi = __uint_as_float((unsigned)(acc[i][j] >> 32));
                int c = 2 * (tc + 16 * j);
                *reinterpret_cast<float2*>(op + c) =
                    make_float2(lo + bv[j].x, hi + bv[j].y);
            }
        }
    }
}

// ---------------------------------------------------------------------------
extern "C" void kernel_launch(void* const* d_in, const int* in_sizes, int n_in,
                              void* d_out, int out_size) {
    const float* feat = (const float*)d_in[0];
    const float* W    = (const float*)d_in[1];
    const float* b    = (const float*)d_in[2];
    const int*   src  = (const int*)d_in[3];
    const int*   dst  = (const int*)d_in[4];
    float*       out  = (float*)d_out;

    int N = in_sizes[0] / D;
    int E = in_sizes[3];
    int SB = (N + 1023) / 1024;

    k_init<<<(N + 255) / 256, 256>>>(N);
    k_total<<<1024, D>>>(feat, N);
    k_degree<<<(E + 255) / 256, 256>>>(dst, E);
    k_scan1<<<SB, 256>>>(N);
    k_scan2<<<1, 128>>>(SB, E, N);
    k_scan3<<<SB, 256>>>(N);
    k_fill<<<(E + 255) / 256, 256>>>(src, dst, E);

    size_t shbytes = (size_t)(D * WTP + 256 * D + 32 * 4) * sizeof(float);
    cudaFuncSetAttribute(k_fused, cudaFuncAttributeMaxDynamicSharedMemorySize, (int)shbytes);
    k_fused<<<(N + 255) / 256, 512, shbytes>>>(W, b, out, N);
}

// round 17
// speedup vs baseline: 1.2058x; 1.2058x over previous
#include <cuda_runtime.h>
#include <cuda_bf16.h>

#define D 128
#define MAX_N 100000
#define MAX_E 1600000
#define WTP 132   // padded W^T row stride (floats); 66 ull per k row

typedef unsigned long long ull;

// Scratch (device globals — no allocations allowed)
__device__ __nv_bfloat16 g_fb[(size_t)MAX_N * D];  // bf16 features
__device__ float g_h[(size_t)MAX_N * D];           // normalized h rows
__device__ float g_total[D];
__device__ int   g_cnt[MAX_N];                     // degrees, then fill cursor
__device__ int   g_off[MAX_N + 1];                 // CSR offsets
__device__ int   g_eidx[MAX_E];                    // src ids bucketed by dst
__device__ int   g_bsum[1024];                     // scan block sums

// Host-side stream/events, created once at program start (host resources only;
// no device memory allocated in kernel_launch).
static cudaStream_t s1;
static cudaEvent_t eF, eB, eG0, eO0;
namespace {
struct HostInit {
    HostInit() {
        cudaStreamCreateWithFlags(&s1, cudaStreamNonBlocking);
        cudaEventCreateWithFlags(&eF,  cudaEventDisableTiming);
        cudaEventCreateWithFlags(&eB,  cudaEventDisableTiming);
        cudaEventCreateWithFlags(&eG0, cudaEventDisableTiming);
        cudaEventCreateWithFlags(&eO0, cudaEventDisableTiming);
    }
};
static HostInit host_init_;
}

// ---------------------------------------------------------------------------
__global__ void k_init(int N) {
    int i = blockIdx.x * blockDim.x + threadIdx.x;
    if (i < N) g_cnt[i] = 0;
    if (i < D) g_total[i] = 0.f;
}

// column sums + bf16 conversion fused (one pass over features)
__global__ void k_total(const float* __restrict__ feat, int N) {
    int c = threadIdx.x;
    float s = 0.f;
    for (int r = blockIdx.x; r < N; r += gridDim.x) {
        float v = feat[(size_t)r * D + c];
        s += v;
        g_fb[(size_t)r * D + c] = __float2bfloat16(v);
    }
    atomicAdd(&g_total[c], s);
}

__global__ void k_degree(const int* __restrict__ dst, int E) {
    int e = blockIdx.x * blockDim.x + threadIdx.x;
    if (e < E) atomicAdd(&g_cnt[dst[e]], 1);
}

// scan1: per-1024-chunk sums
__global__ void k_scan1(int N) {
    __shared__ int ss[256];
    int base = blockIdx.x * 1024;
    int t = threadIdx.x;
    int s = 0;
    #pragma unroll
    for (int j = 0; j < 4; j++) {
        int i = base + t + j * 256;
        if (i < N) s += g_cnt[i];
    }
    ss[t] = s; __syncthreads();
    for (int o = 128; o; o >>= 1) { if (t < o) ss[t] += ss[t + o]; __syncthreads(); }
    if (t == 0) g_bsum[blockIdx.x] = ss[0];
}

// scan2: exclusive scan of block sums, plus g_off[N] = E
__global__ void k_scan2(int SB, int E, int N) {
    __shared__ int ss[1024];
    int t = threadIdx.x;
    for (int i = t; i < SB; i += blockDim.x) ss[i] = g_bsum[i];
    __syncthreads();
    if (t == 0) {
        int run = 0;
        for (int i = 0; i < SB; i++) { int v = ss[i]; ss[i] = run; run += v; }
        g_off[N] = E;
    }
    __syncthreads();
    for (int i = t; i < SB; i += blockDim.x) g_bsum[i] = ss[i];
}

// scan3: per-chunk exclusive scan + global base -> g_off, cursor init
__global__ void k_scan3(int N) {
    __shared__ int ss[256];
    int base = blockIdx.x * 1024;
    int t = threadIdx.x;
    int c[4]; int s = 0;
    #pragma unroll
    for (int j = 0; j < 4; j++) {
        int i = base + t * 4 + j;
        c[j] = (i < N) ? g_cnt[i] : 0;
        s += c[j];
    }
    ss[t] = s; __syncthreads();
    for (int o = 1; o < 256; o <<= 1) {
        int v = (t >= o) ? ss[t - o] : 0;
        __syncthreads();
        ss[t] += v;
        __syncthreads();
    }
    int run = g_bsum[blockIdx.x] + (ss[t] - s);
    #pragma unroll
    for (int j = 0; j < 4; j++) {
        int i = base + t * 4 + j;
        if (i < N) { g_off[i] = run; g_cnt[i] = run; }
        run += c[j];
    }
}

__global__ void k_fill(const int* __restrict__ src, const int* __restrict__ dst, int E) {
    int e = blockIdx.x * blockDim.x + threadIdx.x;
    if (e < E) {
        int pos = atomicAdd(&g_cnt[dst[e]], 1);
        g_eidx[pos] = src[e];
    }
}

// ---------------------------------------------------------------------------
// Gather (bf16 feats) + subtract + L2-normalize, fused. One warp per dst node.
// Processes rows [rowBeg, rowEnd).
// ---------------------------------------------------------------------------
__global__ void k_gather(int rowBeg, int rowEnd) {
    int wid = rowBeg + ((blockIdx.x * blockDim.x + threadIdx.x) >> 5);
    if (wid >= rowEnd) return;
    int lane = threadIdx.x & 31;
    int beg = g_off[wid], end = g_off[wid + 1];

    float4 a0 = make_float4(0.f, 0.f, 0.f, 0.f);
    float4 a1 = make_float4(0.f, 0.f, 0.f, 0.f);
    int e = beg;
    for (; e + 4 <= end; e += 4) {
        int s0 = g_eidx[e], s1v = g_eidx[e + 1], s2 = g_eidx[e + 2], s3 = g_eidx[e + 3];
        ull p0 = *(const ull*)(g_fb + (size_t)s0 * D + lane * 4);
        ull p1 = *(const ull*)(g_fb + (size_t)s1v * D + lane * 4);
        ull p2 = *(const ull*)(g_fb + (size_t)s2 * D + lane * 4);
        ull p3 = *(const ull*)(g_fb + (size_t)s3 * D + lane * 4);
        {
            float2 f0 = __bfloat1622float2(*(__nv_bfloat162*)&p0);
            float2 f1 = __bfloat1622float2(*((__nv_bfloat162*)&p0 + 1));
            a0.x += f0.x; a0.y += f0.y; a0.z += f1.x; a0.w += f1.y;
        }
        {
            float2 f0 = __bfloat1622float2(*(__nv_bfloat162*)&p1);
            float2 f1 = __bfloat1622float2(*((__nv_bfloat162*)&p1 + 1));
            a1.x += f0.x; a1.y += f0.y; a1.z += f1.x; a1.w += f1.y;
        }
        {
            float2 f0 = __bfloat1622float2(*(__nv_bfloat162*)&p2);
            float2 f1 = __bfloat1622float2(*((__nv_bfloat162*)&p2 + 1));
            a0.x += f0.x; a0.y += f0.y; a0.z += f1.x; a0.w += f1.y;
        }
        {
            float2 f0 = __bfloat1622float2(*(__nv_bfloat162*)&p3);
            float2 f1 = __bfloat1622float2(*((__nv_bfloat162*)&p3 + 1));
            a1.x += f0.x; a1.y += f0.y; a1.z += f1.x; a1.w += f1.y;
        }
    }
    for (; e < end; e++) {
        int s0 = g_eidx[e];
        ull p0 = *(const ull*)(g_fb + (size_t)s0 * D + lane * 4);
        float2 f0 = __bfloat1622float2(*(__nv_bfloat162*)&p0);
        float2 f1 = __bfloat1622float2(*((__nv_bfloat162*)&p0 + 1));
        a0.x += f0.x; a0.y += f0.y; a0.z += f1.x; a0.w += f1.y;
    }
    a0.x += a1.x; a0.y += a1.y; a0.z += a1.z; a0.w += a1.w;

    float4 tv = reinterpret_cast<const float4*>(g_total)[lane];
    float4 h;
    h.x = tv.x - a0.x; h.y = tv.y - a0.y; h.z = tv.z - a0.z; h.w = tv.w - a0.w;
    float ss = h.x * h.x + h.y * h.y + h.z * h.z + h.w * h.w;
    #pragma unroll
    for (int o = 16; o; o >>= 1) ss += __shfl_xor_sync(0xffffffffu, ss, o);
    float inv = 1.f / fmaxf(sqrtf(ss), 1e-12f);
    h.x *= inv; h.y *= inv; h.z *= inv; h.w *= inv;
    reinterpret_cast<float4*>(g_h + (size_t)wid * D)[lane] = h;
}

// ---------------------------------------------------------------------------
// GEMM: out = g_h @ W^T + b.  fma.rn.f32x2 paired over OUTPUT COLUMNS.
// 512 threads, 256x128 tile, thread tile = 8 rows x 4 col-pairs (8 cols).
// Covers rows [rowBeg + blockIdx*256, ...) bounded by rowEnd.
// ---------------------------------------------------------------------------
__global__ __launch_bounds__(512, 1)
void k_out(const float* __restrict__ W, const float* __restrict__ b,
           float* __restrict__ out, int rowBeg, int rowEnd) {
    extern __shared__ float sh[];
    float* shWT = sh;                              // [D][WTP]
    float* shH  = sh + D * WTP;                    // [256][128] + skew 4/8rows
    const ull* shWTu = reinterpret_cast<const ull*>(shWT);

    int tid = threadIdx.x;

    // Stage W transposed: shWT[k*WTP + c] = W[c][k]
    for (int idx = tid; idx < D * D; idx += 512) {
        int c = idx >> 7;
        int k = idx & (D - 1);
        shWT[k * WTP + c] = W[idx];
    }

    int row0 = rowBeg + blockIdx.x * 256;
    // Stage H tile with skew (zero-pad OOB rows)
    for (int idx = tid; idx < 256 * 32; idx += 512) {
        int r = idx >> 5, c4 = idx & 31;
        int row = row0 + r;
        float4 v = make_float4(0.f, 0.f, 0.f, 0.f);
        if (row < rowEnd) v = reinterpret_cast<const float4*>(g_h + (size_t)row * D)[c4];
        *reinterpret_cast<float4*>(shH + r * D + (r >> 3) * 4 + c4 * 4) = v;
    }
    __syncthreads();

    int tr = tid >> 4;       // 0..31 -> rows tr*8..+7
    int tc = tid & 15;       // col-pairs tc + 16*j, j=0..3

    ull acc[8][4];
    #pragma unroll
    for (int i = 0; i < 8; i++)
        #pragma unroll
        for (int j = 0; j < 4; j++) acc[i][j] = 0ull;

    const float* hbase = shH + (tr << 3) * D + (tr << 2);   // skew = tr*4
    const ull* wbase = shWTu + tc;

    #pragma unroll 2
    for (int k = 0; k < D; k++) {
        ull wv[4];
        const ull* wrow = wbase + k * (WTP / 2);
        #pragma unroll
        for (int j = 0; j < 4; j++) wv[j] = wrow[16 * j];
        #pragma unroll
        for (int i = 0; i < 8; i++) {
            float hs = hbase[i * D + k];
            ull hd;
            asm("mov.b64 %0, {%1, %1};" : "=l"(hd) : "f"(hs));
            #pragma unroll
            for (int j = 0; j < 4; j++)
                asm("fma.rn.f32x2 %0, %1, %2, %0;"
                    : "+l"(acc[i][j]) : "l"(hd), "l"(wv[j]));
        }
    }

    float2 bv[4];
    #pragma unroll
    for (int j = 0; j < 4; j++)
        bv[j] = *reinterpret_cast<const float2*>(b + 2 * (tc + 16 * j));

    #pragma unroll
    for (int i = 0; i < 8; i++) {
        int row = row0 + (tr << 3) + i;
        if (row < rowEnd) {
            float* op = out + (size_t)row * D;
            #pragma unroll
            for (int j = 0; j < 4; j++) {
                float lo = __uint_as_float((unsigned)(acc[i][j] & 0xffffffffu));
                float hi = __uint_as_float((unsigned)(acc[i][j] >> 32));
                int c = 2 * (tc + 16 * j);
                *reinterpret_cast<float2*>(op + c) =
                    make_float2(lo + bv[j].x, hi + bv[j].y);
            }
        }
    }
}

// ---------------------------------------------------------------------------
extern "C" void kernel_launch(void* const* d_in, const int* in_sizes, int n_in,
                              void* d_out, int out_size) {
    const float* feat = (const float*)d_in[0];
    const float* W    = (const float*)d_in[1];
    const float* b    = (const float*)d_in[2];
    const int*   src  = (const int*)d_in[3];
    const int*   dst  = (const int*)d_in[4];
    float*       out  = (float*)d_out;

    int N = in_sizes[0] / D;
    int E = in_sizes[3];
    int SB = (N + 1023) / 1024;

    size_t shbytes = (size_t)(D * WTP + 256 * D + 32 * 4) * sizeof(float);
    cudaFuncSetAttribute(k_out, cudaFuncAttributeMaxDynamicSharedMemorySize, (int)shbytes);

    int tiles = (N + 255) / 256;
    int t0 = tiles / 2;              // first-half tiles
    int N2 = t0 * 256;               // first-half row boundary (multiple of 256)

    // ---- L (legacy stream): init, then fork int chain to s1 ----
    k_init<<<(N + 255) / 256, 256>>>(N);
    cudaEventRecord(eF, 0);
    cudaStreamWaitEvent(s1, eF, 0);

    // Chain B on s1: degree -> scans -> fill
    k_degree<<<(E + 255) / 256, 256, 0, s1>>>(dst, E);
    k_scan1<<<SB, 256, 0, s1>>>(N);
    k_scan2<<<1, 128, 0, s1>>>(SB, E, N);
    k_scan3<<<SB, 256, 0, s1>>>(N);
    k_fill<<<(E + 255) / 256, 256, 0, s1>>>(src, dst, E);
    cudaEventRecord(eB, s1);

    // Chain A on L, concurrent with chain B
    k_total<<<1024, D>>>(feat, N);

    // Join: gather needs both chains
    cudaStreamWaitEvent(0, eB, 0);

    if (t0 > 0 && N2 < N) {
        // gather half0 on L
        k_gather<<<(N2 * 32 + 255) / 256, 256>>>(0, N2);
        cudaEventRecord(eG0, 0);
        // gather half1 on L (in-order after half0)
        k_gather<<<((N - N2) * 32 + 255) / 256, 256>>>(N2, N);
        // out half0 on s1, concurrent with gather half1
        cudaStreamWaitEvent(s1, eG0, 0);
        k_out<<<t0, 512, shbytes, s1>>>(W, b, out, 0, N2);
        cudaEventRecord(eO0, s1);
        // out half1 on L (after gather half1 in-order)
        k_out<<<tiles - t0, 512, shbytes>>>(W, b, out, N2, N);
        // join s1 back before return
        cudaStreamWaitEvent(0, eO0, 0);
    } else {
        k_gather<<<((long long)N * 32 + 255) / 256, 256>>>(0, N);
        k_out<<<tiles, 512, shbytes>>>(W, b, out, 0, N);
    }
}